// round 17
// baseline (speedup 1.0000x reference)
#include <cuda_runtime.h>
#include <cuda_fp16.h>

#define Bn 2
#define H 384
#define W 1280
#define HW (H * W)
#define BHW (Bn * H * W)

// Persistent kernel, full-width bands: tile = 1280 x 6, grid = 64 bands x 2 batches.
// 3 layers x 2 adjacent rows per thread; d lives in registers.
#define TH 6
#define SPR (W / 4)             // strips per row = 320
#define NSTRIP (SPR * TH)       // 1920 strips per tile
#define THREADS 960             // 320 cols x 3 layers
#define NBANDS (H / TH)         // 64
#define NBLK (NBANDS * Bn)      // 128 blocks, all co-resident (< 148 SMs, 1 blk/SM)
#define ITERS 24

#define S_W_BYTES  (NSTRIP * 64)     // 122880: fp16 weights, [p][strip]
#define S_C_BYTES  (NSTRIP * 16)     // 30720:  C as float4 per strip
#define S_EDGE_FL2 (TH * SPR)        // 1920 float2 per buffer (15360 B)
#define S_IF_FL4   (4 * SPR)         // 1280 float4 per buffer (20480 B)
#define SMEM_BYTES (S_W_BYTES + S_C_BYTES + 2 * S_EDGE_FL2 * 8 + 2 * S_IF_FL4 * 16) // 225280

// Persistent scratch (no allocations allowed in kernel_launch).
__device__ __half   g_wh[(size_t)8 * BHW];  // fp16 weights, pixel-major [pix][k0..k7]
__device__ float    g_c[BHW];               // constant term per pixel
__device__ float    g_d0[BHW];              // publish buffer (odd iters)
__device__ float    g_d1[BHW];              // publish buffer (even iters)
__device__ unsigned g_flag[NBLK];           // per-block iteration flags (reset by prep)

// Neighbor offsets per channel k (derived from PADS):
// k0:(+1,+1) k1:(+1,0) k2:(+1,-1) k3:(0,+1) k4:(0,-1) k5:(-1,+1) k6:(-1,0) k7:(-1,-1)
__constant__ int c_di[8] = { 1, 1, 1, 0, 0, -1, -1, -1 };
__constant__ int c_dj[8] = { 1, 0, -1, 1, -1, 1, 0, -1 };

__global__ void prep_kernel(const float* __restrict__ guid,
                            const float* __restrict__ blur,
                            const float* __restrict__ sparse) {
    int idx = blockIdx.x * blockDim.x + threadIdx.x;
    if (idx < NBLK) g_flag[idx] = 0;         // reset neighbor flags every call
    if (idx >= BHW) return;
    int j = idx % W;
    int t = idx / W;
    int i = t % H;
    int b = t / H;

    float v[8];
    float den = 0.0f;
#pragma unroll
    for (int k = 0; k < 8; k++) {
        int ni = i + c_di[k];
        int nj = j + c_dj[k];
        float val = 0.0f;
        if (ni >= 0 && ni < H && nj >= 0 && nj < W)
            val = guid[((b * 8 + k) * H + ni) * W + nj];
        v[k] = val;
        den += fabsf(val);
    }
    float inv = 1.0f / (den + 1e-9f);
    float gs = 0.0f;
#pragma unroll
    for (int k = 0; k < 8; k++) {
        v[k] *= inv;
        gs += v[k];
    }
    float m = (sparse[idx] > 0.0f) ? 1.0f : 0.0f;
    float fac = 1.0f - m;
    float raw = blur[idx];
    g_c[idx] = (fac * (1.0f - gs) + m) * raw;

    // Pack 8 fp16 weights per pixel (16B). OOB weights are exactly 0 in fp16 too.
    __half2 h0 = __floats2half2_rn(fac * v[0], fac * v[1]);
    __half2 h1 = __floats2half2_rn(fac * v[2], fac * v[3]);
    __half2 h2 = __floats2half2_rn(fac * v[4], fac * v[5]);
    __half2 h3 = __floats2half2_rn(fac * v[6], fac * v[7]);
    uint4 pack;
    pack.x = *reinterpret_cast<unsigned int*>(&h0);
    pack.y = *reinterpret_cast<unsigned int*>(&h1);
    pack.z = *reinterpret_cast<unsigned int*>(&h2);
    pack.w = *reinterpret_cast<unsigned int*>(&h3);
    *reinterpret_cast<uint4*>(g_wh + (size_t)idx * 8) = pack;
}

// Stencil for one 4-px row strip from prebuilt 6-wide rows.
// up/mi/dn = {col j0-1, j0..j0+3, j0+4} of rows r-1, r, r+1.
__device__ __forceinline__ float4 row_calc(const uint4* __restrict__ s_w,
                                           const float4* __restrict__ s_c, int st,
                                           const float* up, const float* mi,
                                           const float* dn) {
    float4 cc = s_c[st];
    float cv[4] = { cc.x, cc.y, cc.z, cc.w };
    float o[4];
#pragma unroll
    for (int p = 0; p < 4; p++) {
        uint4 wv = s_w[p * NSTRIP + st];
        __half2 h0 = *reinterpret_cast<__half2*>(&wv.x);
        __half2 h1 = *reinterpret_cast<__half2*>(&wv.y);
        __half2 h2 = *reinterpret_cast<__half2*>(&wv.z);
        __half2 h3 = *reinterpret_cast<__half2*>(&wv.w);
        float2 w01 = __half22float2(h0);   // k0, k1
        float2 w23 = __half22float2(h1);   // k2, k3
        float2 w45 = __half22float2(h2);   // k4, k5
        float2 w67 = __half22float2(h3);   // k6, k7

        float acc = cv[p];
        acc = fmaf(w01.x, dn[p + 2], acc);   // (+1,+1)
        acc = fmaf(w01.y, dn[p + 1], acc);   // (+1, 0)
        acc = fmaf(w23.x, dn[p],     acc);   // (+1,-1)
        acc = fmaf(w23.y, mi[p + 2], acc);   // ( 0,+1)
        acc = fmaf(w45.x, mi[p],     acc);   // ( 0,-1)
        acc = fmaf(w45.y, up[p + 2], acc);   // (-1,+1)
        acc = fmaf(w67.x, up[p + 1], acc);   // (-1, 0)
        acc = fmaf(w67.y, up[p],     acc);   // (-1,-1)
        o[p] = acc;
    }
    return make_float4(o[0], o[1], o[2], o[3]);
}

__device__ __forceinline__ void halo6(const float* __restrict__ hrow, int j0, float v[6]) {
    v[0] = hrow[(j0 > 0) ? (j0 - 1) : 0];
    float4 h = *reinterpret_cast<const float4*>(hrow + j0);
    v[1] = h.x; v[2] = h.y; v[3] = h.z; v[4] = h.w;
    v[5] = hrow[(j0 + 4 < W) ? (j0 + 4) : (W - 1)];
}

// Persistent kernel: 24 sweeps in one launch. Each thread keeps its 2 adjacent rows
// (8 px) in registers; smem carries weights, C, per-row edge columns, and the 4
// interface rows, double-buffered by parity. Inter-block sync is NEIGHBOR-ONLY:
// per-block release flags, each block waits just for band-1 / band+1.
__global__ __launch_bounds__(THREADS, 1)
void prop_persist(const float* __restrict__ blur, float* __restrict__ out) {
    extern __shared__ char sm[];
    uint4*  s_w    = reinterpret_cast<uint4*>(sm);
    float4* s_c    = reinterpret_cast<float4*>(sm + S_W_BYTES);
    float2* s_edge = reinterpret_cast<float2*>(sm + S_W_BYTES + S_C_BYTES);            // [2][TH][SPR]
    float4* s_if   = reinterpret_cast<float4*>(sm + S_W_BYTES + S_C_BYTES
                                               + 2 * S_EDGE_FL2 * 8);                  // [2][4][SPR]

    const int tid  = threadIdx.x;
    const int rp   = tid / SPR;                  // layer 0..2
    const int c    = tid - rp * SPR;             // column strip 0..319
    const int j0   = c * 4;
    const int band = blockIdx.x;
    const int b    = blockIdx.y;
    const int ti   = band * TH;
    const int fi   = b * NBANDS + band;          // this block's flag index
    const bool hasTop = (band > 0);
    const bool hasBot = (band < NBANDS - 1);
    const int ra   = 2 * rp, rb = ra + 1;        // owned rows within band
    const int cm   = (c > 0) ? c - 1 : 0;        // clamped neighbors (image edge: w==0)
    const int cp   = (c < SPR - 1) ? c + 1 : SPR - 1;

    // ---- prologue: stage weights (transposed [p][strip]) + C
    for (int st = tid; st < NSTRIP; st += THREADS) {
        int r = st / SPR, cq = st - r * SPR;
        int gp = (b * H + ti + r) * W + cq * 4;
        const uint4* wsrc = reinterpret_cast<const uint4*>(g_wh + (size_t)gp * 8);
#pragma unroll
        for (int p = 0; p < 4; p++) s_w[p * NSTRIP + st] = wsrc[p];
        s_c[st] = *reinterpret_cast<const float4*>(g_c + gp);
    }
    // own rows into registers, initial edge/iface into buffer 0
    float4 dA = *reinterpret_cast<const float4*>(blur + (size_t)(b * H + ti + ra) * W + j0);
    float4 dB = *reinterpret_cast<const float4*>(blur + (size_t)(b * H + ti + rb) * W + j0);
    s_edge[ra * SPR + c] = make_float2(dA.x, dA.w);
    s_edge[rb * SPR + c] = make_float2(dB.x, dB.w);
    if (rp == 0)      { s_if[0 * SPR + c] = dB; }                          // row 1
    else if (rp == 1) { s_if[1 * SPR + c] = dA; s_if[2 * SPR + c] = dB; }  // rows 2,3
    else              { s_if[3 * SPR + c] = dA; }                          // row 4
    __syncthreads();

    for (int it = 1; it <= ITERS; ++it) {
        const int rd = (it - 1) & 1, wr = it & 1;
        const float2* eg = s_edge + rd * S_EDGE_FL2;
        const float4* fc = s_if   + rd * S_IF_FL4;
        const bool last = (it == ITERS);
        const float* haloSrc = (it == 1) ? blur : ((it & 1) ? g_d0 : g_d1);  // pub(it-1)

        // own rows as 6-wide arrays (edges from smem)
        float a6[6] = { eg[ra * SPR + cm].y, dA.x, dA.y, dA.z, dA.w, eg[ra * SPR + cp].x };
        float b6[6] = { eg[rb * SPR + cm].y, dB.x, dB.y, dB.z, dB.w, eg[rb * SPR + cp].x };

        float4 nA, nB;

        // ---- phase A: rows 1..4 (no inter-block dependency)
        if (rp == 0) {
            float4 f = fc[1 * SPR + c];                                    // row 2
            float d6[6] = { eg[2 * SPR + cm].y, f.x, f.y, f.z, f.w, eg[2 * SPR + cp].x };
            nB = row_calc(s_w, s_c, 1 * SPR + c, a6, b6, d6);              // row 1
        } else if (rp == 1) {
            float4 f1 = fc[0 * SPR + c];                                   // row 1
            float u6[6] = { eg[1 * SPR + cm].y, f1.x, f1.y, f1.z, f1.w, eg[1 * SPR + cp].x };
            nA = row_calc(s_w, s_c, 2 * SPR + c, u6, a6, b6);              // row 2
            float4 f4 = fc[3 * SPR + c];                                   // row 4
            float d6[6] = { eg[4 * SPR + cm].y, f4.x, f4.y, f4.z, f4.w, eg[4 * SPR + cp].x };
            nB = row_calc(s_w, s_c, 3 * SPR + c, a6, b6, d6);              // row 3
        } else {
            float4 f3 = fc[2 * SPR + c];                                   // row 3
            float u6[6] = { eg[3 * SPR + cm].y, f3.x, f3.y, f3.z, f3.w, eg[3 * SPR + cp].x };
            nA = row_calc(s_w, s_c, 4 * SPR + c, u6, a6, b6);              // row 4
        }

        // ---- neighbor-only wait: band±1 must have published iter it-1
        if (it > 1) {
            if (tid == 0) {
                volatile unsigned* vf = g_flag;
                unsigned need = (unsigned)(it - 1);
                if (hasTop) while (vf[fi - 1] < need) __nanosleep(32);
                if (hasBot) while (vf[fi + 1] < need) __nanosleep(32);
                __threadfence();                 // acquire neighbors' published rows
            }
            __syncthreads();
        }

        // ---- phase B: boundary rows 0 and 5 using neighbors' published halo rows
        if (rp == 0) {
            float u6[6];
            if (!hasTop) {                        // image top: up-weights are 0
#pragma unroll
                for (int q = 0; q < 6; q++) u6[q] = a6[q];
            } else {
                halo6(haloSrc + (size_t)(b * H + ti - 1) * W, j0, u6);
            }
            nA = row_calc(s_w, s_c, 0 * SPR + c, u6, a6, b6);              // row 0
        } else if (rp == 2) {
            float d6[6];
            if (!hasBot) {                        // image bottom: down-weights are 0
#pragma unroll
                for (int q = 0; q < 6; q++) d6[q] = b6[q];
            } else {
                halo6(haloSrc + (size_t)(b * H + ti + TH) * W, j0, d6);
            }
            nB = row_calc(s_w, s_c, 5 * SPR + c, a6, b6, d6);              // row 5
        }

        // ---- write back
        if (last) {
            *reinterpret_cast<float4*>(out + (size_t)(b * H + ti + ra) * W + j0) = nA;
            *reinterpret_cast<float4*>(out + (size_t)(b * H + ti + rb) * W + j0) = nB;
        } else {
            float* pub = (it & 1) ? g_d1 : g_d0;  // pub(it)
            if (rp == 0) {
                *reinterpret_cast<float4*>(pub + (size_t)(b * H + ti) * W + j0) = nA;
                __threadfence();                  // release published row before flag
            }
            if (rp == 2) {
                *reinterpret_cast<float4*>(pub + (size_t)(b * H + ti + TH - 1) * W + j0) = nB;
                __threadfence();                  // release published row before flag
            }

            float2* egw = s_edge + wr * S_EDGE_FL2;
            float4* fcw = s_if   + wr * S_IF_FL4;
            egw[ra * SPR + c] = make_float2(nA.x, nA.w);
            egw[rb * SPR + c] = make_float2(nB.x, nB.w);
            if (rp == 0)      { fcw[0 * SPR + c] = nB; }
            else if (rp == 1) { fcw[1 * SPR + c] = nA; fcw[2 * SPR + c] = nB; }
            else              { fcw[3 * SPR + c] = nA; }

            __syncthreads();                      // publishes + smem writes done
            if (tid == 0) g_flag[fi] = (unsigned)it;   // arrive (release)
            dA = nA; dB = nB;
        }
    }
}

extern "C" void kernel_launch(void* const* d_in, const int* in_sizes, int n_in,
                              void* d_out, int out_size) {
    const float* guid   = (const float*)d_in[0];   // (B, 8, H, W)
    const float* blur   = (const float*)d_in[1];   // (B, 1, H, W)
    const float* sparse = (const float*)d_in[2];   // (B, 1, H, W)
    float* out = (float*)d_out;                    // (B, H, W)

    cudaFuncSetAttribute(prop_persist,
                         cudaFuncAttributeMaxDynamicSharedMemorySize, SMEM_BYTES);

    prep_kernel<<<(BHW + 255) / 256, 256>>>(guid, blur, sparse);

    dim3 grid(NBANDS, Bn, 1);                      // (64, 2) = 128 blocks
    prop_persist<<<grid, THREADS, SMEM_BYTES>>>(blur, out);
}